// round 8
// baseline (speedup 1.0000x reference)
#include <cuda_runtime.h>

#define NT   10
#define DIMX 240
#define NSC  64
#define NF   112
#define EPSV 1e-5f
#define RS   4           // replicated accumulator copies (row-subgroups)
#define NBLK 592         // one full wave: 148 SMs x 4 CTAs

// scratch layout: [sum2: NT*DIMX][sum1: NT*NSC][cnt: NT]
#define SCR_SUM1 (NT*DIMX)
#define SCR_CNT  (NT*DIMX + NT*NSC)
#define SCR_SIZE (NT*DIMX + NT*NSC + NT)

__device__ float g_scr[SCR_SIZE];
__device__ __align__(16) float g_A[NT*DIMX];
__device__ __align__(16) float g_B[NT*DIMX];

// ---------------------------------------------------------------- zero scratch
__global__ void k_zero() {
    int i = blockIdx.x * blockDim.x + threadIdx.x;
    if (i < SCR_SIZE) g_scr[i] = 0.0f;
}

// packed-f32x2 shared-memory RMW: s[0..3] += v*v
__device__ __forceinline__ void rmw_fma2(unsigned sa, unsigned long long v01,
                                         unsigned long long v23) {
    asm volatile(
        "{\n\t"
        ".reg .b64 a0, a1;\n\t"
        "ld.shared.v2.b64 {a0, a1}, [%0];\n\t"
        "fma.rn.f32x2 a0, %1, %1, a0;\n\t"
        "fma.rn.f32x2 a1, %2, %2, a1;\n\t"
        "st.shared.v2.b64 [%0], {a0, a1};\n\t"
        "}"
        :: "r"(sa), "l"(v01), "l"(v23));
}

// packed-f32x2 shared-memory RMW: s[0..3] += v
__device__ __forceinline__ void rmw_add2(unsigned sa, unsigned long long v01,
                                         unsigned long long v23) {
    asm volatile(
        "{\n\t"
        ".reg .b64 a0, a1;\n\t"
        "ld.shared.v2.b64 {a0, a1}, [%0];\n\t"
        "add.rn.f32x2 a0, a0, %1;\n\t"
        "add.rn.f32x2 a1, a1, %2;\n\t"
        "st.shared.v2.b64 [%0], {a0, a1};\n\t"
        "}"
        :: "r"(sa), "l"(v01), "l"(v23));
}

// ---------------------------------------------------------------- stats pass
// Block b owns contiguous rows [b*chunk, b*chunk+chunk). blockDim=256,
// threads 0..239 active.
//   rs = tid/60 : accumulator copy; handles rows base+8*rs .. base+8*rs+7
//   c4 = tid%60 : float4 column group
// 32 rows per CTA-iteration; types fetched 4-at-a-time via int4.
__global__ __launch_bounds__(256, 4) void k_stats(const float* __restrict__ x,
                                                  const int* __restrict__ ty,
                                                  int batch, int chunk) {
    __shared__ __align__(16) float s2[RS * NT * DIMX];
    __shared__ __align__(16) float s1[RS * NT * NSC];
    __shared__ float scnt[RS * NT];

    const int tid = threadIdx.x;
    for (int i = tid; i < RS * NT * DIMX; i += 256) s2[i] = 0.0f;
    for (int i = tid; i < RS * NT * NSC;  i += 256) s1[i] = 0.0f;
    if (tid < RS * NT) scnt[tid] = 0.0f;
    __syncthreads();

    const int  rs  = tid / 60;
    const int  c4  = tid - rs * 60;
    const int  c   = c4 * 4;
    const bool act = (tid < 240);
    const bool sc  = act && (c4 < 16);   // scalar columns
    const bool cn  = act && (c4 == 0);   // count owner

    const unsigned sa2 = (unsigned)__cvta_generic_to_shared(s2)
                       + (rs * NT * DIMX + c) * 4u;
    const unsigned sa1 = (unsigned)__cvta_generic_to_shared(s1)
                       + (rs * NT * NSC + c) * 4u;

    const int rowLo  = blockIdx.x * chunk;
    const int rowHi  = min(batch, rowLo + chunk);

    for (int base = rowLo; base < rowHi; base += 32) {
        if (act) {
            const int r0 = base + rs * 8;          // this thread's 8 rows
            ulonglong2 u[8];
            int  t[8];
            bool g[8];
#pragma unroll
            for (int i = 0; i < 8; i++) {
                int r = r0 + i;
                g[i] = (r < batch);
                if (g[i]) u[i] = __ldg((const ulonglong2*)(x + (size_t)r * DIMX + c));
            }
            // types: 2x int4 (rows r0..r0+3, r0+4..r0+7), guarded for tail
            if (r0 + 7 < batch) {
                int4 ta = __ldg((const int4*)(ty + r0));
                int4 tb = __ldg((const int4*)(ty + r0 + 4));
                t[0]=ta.x; t[1]=ta.y; t[2]=ta.z; t[3]=ta.w;
                t[4]=tb.x; t[5]=tb.y; t[6]=tb.z; t[7]=tb.w;
            } else {
#pragma unroll
                for (int i = 0; i < 8; i++) t[i] = g[i] ? __ldg(ty + r0 + i) : 0;
            }
#pragma unroll
            for (int i = 0; i < 8; i++) {
                if (g[i]) {
                    rmw_fma2(sa2 + t[i] * (DIMX * 4), u[i].x, u[i].y);
                    if (sc) rmw_add2(sa1 + t[i] * (NSC * 4), u[i].x, u[i].y);
                    if (cn) scnt[rs * NT + t[i]] += 1.0f;
                }
            }
        }
    }
    __syncthreads();

    // reduce RS copies, push to global with atomics
    for (int i = tid; i < NT * DIMX; i += 256) {
        float s = s2[i] + s2[NT*DIMX + i] + s2[2*NT*DIMX + i] + s2[3*NT*DIMX + i];
        atomicAdd(&g_scr[i], s);
    }
    for (int i = tid; i < NT * NSC; i += 256) {
        float s = s1[i] + s1[NT*NSC + i] + s1[2*NT*NSC + i] + s1[3*NT*NSC + i];
        atomicAdd(&g_scr[SCR_SUM1 + i], s);
    }
    if (tid < NT) {
        float s = scnt[tid] + scnt[NT + tid] + scnt[2*NT + tid] + scnt[3*NT + tid];
        atomicAdd(&g_scr[SCR_CNT + tid], s);
    }
}

// ---------------------------------------------------------------- table build
__global__ __launch_bounds__(DIMX) void k_tables(const float* __restrict__ w,
                                                 const float* __restrict__ b) {
    const int e = threadIdx.x;
    for (int t = 0; t < NT; t++) {
        float cnt = fmaxf(g_scr[SCR_CNT + t], 1.0f);
        float inv = 1.0f / cnt;
        float A, Bv;
        if (e < NSC) {
            float S2   = g_scr[t * DIMX + e];
            float S1   = g_scr[SCR_SUM1 + t * NSC + e];
            float mean = S1 * inv;
            float var  = S2 * inv - mean * mean;
            float s    = rsqrtf(var + EPSV) * w[t * NF + e];
            A  = s;
            Bv = b[t * NSC + e] - mean * s;
        } else if (e < 64 + 32 * 3) {
            int m    = (e - 64) / 3;
            int base = 64 + m * 3;
            float S2 = g_scr[t * DIMX + base] + g_scr[t * DIMX + base + 1] +
                       g_scr[t * DIMX + base + 2];
            float fn = S2 * inv * (1.0f / 3.0f);
            A  = rsqrtf(fn + EPSV) * w[t * NF + 64 + m];
            Bv = 0.0f;
        } else {
            int m    = (e - 160) / 5;
            int base = 160 + m * 5;
            float S2 = 0.0f;
#pragma unroll
            for (int j = 0; j < 5; j++) S2 += g_scr[t * DIMX + base + j];
            float fn = S2 * inv * 0.2f;
            A  = rsqrtf(fn + EPSV) * w[t * NF + 96 + m];
            Bv = 0.0f;
        }
        g_A[t * DIMX + e] = A;
        g_B[t * DIMX + e] = Bv;
    }
}

// ---------------------------------------------------------------- apply pass
// Block b owns the SAME rows stats block b owned, walked in DESCENDING 8 KB
// tiles: the chunk tail is exactly what stats left most-recent in L2.
// Streaming stores keep the output from evicting the x residue.
__global__ __launch_bounds__(256) void k_apply(const float4* __restrict__ x4,
                                               const int* __restrict__ ty,
                                               float4* __restrict__ o4,
                                               int batch, int chunk) {
    const int rowLo = blockIdx.x * chunk;
    const int rowHi = min(batch, rowLo + chunk);
    if (rowLo >= rowHi) return;

    const int lo = rowLo * 60;           // first float4 index of chunk
    const int hi = rowHi * 60;           // one-past-last

    const float4* A4 = reinterpret_cast<const float4*>(g_A);
    const float4* B4 = reinterpret_cast<const float4*>(g_B);

    const int nTiles = (hi - lo + 511) / 512;
    for (int tile = nTiles - 1; tile >= 0; tile--) {
        const unsigned i0 = (unsigned)(lo + tile * 512) + threadIdx.x;
        const unsigned i1 = i0 + 256u;
        const bool g0 = i0 < (unsigned)hi;
        const bool g1 = i1 < (unsigned)hi;

        float4 xv0, xv1, a0, a1, b0, b1;
        unsigned k0 = 0, k1 = 0;

        if (g0) {
            unsigned row = i0 / 60u;
            unsigned q   = i0 - row * 60u;
            int t = __ldg(ty + row);
            k0  = t * 60u + q;
            xv0 = x4[i0];
        }
        if (g1) {
            unsigned row = i1 / 60u;
            unsigned q   = i1 - row * 60u;
            int t = __ldg(ty + row);
            k1  = t * 60u + q;
            xv1 = x4[i1];
        }
        if (g0) { a0 = A4[k0]; b0 = B4[k0]; }
        if (g1) { a1 = A4[k1]; b1 = B4[k1]; }

        if (g0) {
            float4 o;
            o.x = fmaf(xv0.x, a0.x, b0.x);
            o.y = fmaf(xv0.y, a0.y, b0.y);
            o.z = fmaf(xv0.z, a0.z, b0.z);
            o.w = fmaf(xv0.w, a0.w, b0.w);
            __stcs(&o4[i0], o);
        }
        if (g1) {
            float4 o;
            o.x = fmaf(xv1.x, a1.x, b1.x);
            o.y = fmaf(xv1.y, a1.y, b1.y);
            o.z = fmaf(xv1.z, a1.z, b1.z);
            o.w = fmaf(xv1.w, a1.w, b1.w);
            __stcs(&o4[i1], o);
        }
    }
}

// ---------------------------------------------------------------- launch
extern "C" void kernel_launch(void* const* d_in, const int* in_sizes, int n_in,
                              void* d_out, int out_size) {
    const float* x  = (const float*)d_in[0];
    const int*   ty = (const int*)d_in[1];
    const float* w  = (const float*)d_in[2];
    const float* b  = (const float*)d_in[3];

    int batch = in_sizes[0] / DIMX;
    // rows per block, multiple of 32, covering batch with NBLK blocks
    int chunk = ((batch + NBLK * 32 - 1) / (NBLK * 32)) * 32;

    k_zero<<<(SCR_SIZE + 255) / 256, 256>>>();
    k_stats<<<NBLK, 256>>>(x, ty, batch, chunk);
    k_tables<<<1, DIMX>>>(w, b);
    k_apply<<<NBLK, 256>>>((const float4*)x, ty, (float4*)d_out, batch, chunk);
}

// round 9
// speedup vs baseline: 1.1378x; 1.1378x over previous
#include <cuda_runtime.h>

#define NT   10
#define DIMX 240
#define NSC  64
#define NF   112
#define EPSV 1e-5f
#define RS   4           // replicated accumulator copies (row-subgroups)

// scratch layout: [sum2: NT*DIMX][sum1: NT*NSC][cnt: NT]
#define SCR_SUM1 (NT*DIMX)
#define SCR_CNT  (NT*DIMX + NT*NSC)
#define SCR_SIZE (NT*DIMX + NT*NSC + NT)

__device__ float g_scr[SCR_SIZE];
__device__ __align__(16) float g_A[NT*DIMX];
__device__ __align__(16) float g_B[NT*DIMX];

// ---------------------------------------------------------------- zero scratch
__global__ void k_zero() {
    int i = blockIdx.x * blockDim.x + threadIdx.x;
    if (i < SCR_SIZE) g_scr[i] = 0.0f;
}

// packed-f32x2 shared-memory RMW: s[0..3] += v*v
__device__ __forceinline__ void rmw_fma2(unsigned sa, unsigned long long v01,
                                         unsigned long long v23) {
    asm volatile(
        "{\n\t"
        ".reg .b64 a0, a1;\n\t"
        "ld.shared.v2.b64 {a0, a1}, [%0];\n\t"
        "fma.rn.f32x2 a0, %1, %1, a0;\n\t"
        "fma.rn.f32x2 a1, %2, %2, a1;\n\t"
        "st.shared.v2.b64 [%0], {a0, a1};\n\t"
        "}"
        :: "r"(sa), "l"(v01), "l"(v23));
}

// packed-f32x2 shared-memory RMW: s[0..3] += v
__device__ __forceinline__ void rmw_add2(unsigned sa, unsigned long long v01,
                                         unsigned long long v23) {
    asm volatile(
        "{\n\t"
        ".reg .b64 a0, a1;\n\t"
        "ld.shared.v2.b64 {a0, a1}, [%0];\n\t"
        "add.rn.f32x2 a0, a0, %1;\n\t"
        "add.rn.f32x2 a1, a1, %2;\n\t"
        "st.shared.v2.b64 [%0], {a0, a1};\n\t"
        "}"
        :: "r"(sa), "l"(v01), "l"(v23));
}

// ---------------------------------------------------------------- stats pass
// Grid-strided, blockDim = 256 (threads 0..239 active).
//   rs = tid/60 : accumulator copy; owns rows base+4*rs .. base+4*rs+3
//   c4 = tid%60 : float4 column group
// 16 rows per CTA-iteration; the thread's 4 rows are CONTIGUOUS so one int4
// load fetches all 4 types. Exclusive (rs, column) ownership -> no atomics.
__global__ __launch_bounds__(256) void k_stats(const float* __restrict__ x,
                                               const int* __restrict__ ty,
                                               int batch) {
    __shared__ __align__(16) float s2[RS * NT * DIMX];
    __shared__ __align__(16) float s1[RS * NT * NSC];
    __shared__ float scnt[RS * NT];

    const int tid = threadIdx.x;
    for (int i = tid; i < RS * NT * DIMX; i += 256) s2[i] = 0.0f;
    for (int i = tid; i < RS * NT * NSC;  i += 256) s1[i] = 0.0f;
    if (tid < RS * NT) scnt[tid] = 0.0f;
    __syncthreads();

    const int  rs  = tid / 60;
    const int  c4  = tid - rs * 60;
    const int  c   = c4 * 4;
    const bool act = (tid < 240);
    const bool sc  = act && (c4 < 16);   // scalar columns
    const bool cn  = act && (c4 == 0);   // count owner

    const unsigned sa2 = (unsigned)__cvta_generic_to_shared(s2)
                       + (rs * NT * DIMX + c) * 4u;
    const unsigned sa1 = (unsigned)__cvta_generic_to_shared(s1)
                       + (rs * NT * NSC + c) * 4u;

    const int step = gridDim.x * 16;
    for (int base = blockIdx.x * 16; base < batch; base += step) {
        if (act) {
            const int r0 = base + rs * 4;        // 4 contiguous rows
            ulonglong2 u[4];
            int  t[4];
            bool g[4];
#pragma unroll
            for (int i = 0; i < 4; i++) {
                int r = r0 + i;
                g[i] = (r < batch);
                if (g[i]) u[i] = __ldg((const ulonglong2*)(x + (size_t)r * DIMX + c));
            }
            if (r0 + 3 < batch) {
                int4 ta = __ldg((const int4*)(ty + r0));
                t[0] = ta.x; t[1] = ta.y; t[2] = ta.z; t[3] = ta.w;
            } else {
#pragma unroll
                for (int i = 0; i < 4; i++) t[i] = g[i] ? __ldg(ty + r0 + i) : 0;
            }
#pragma unroll
            for (int i = 0; i < 4; i++) {
                if (g[i]) {
                    rmw_fma2(sa2 + t[i] * (DIMX * 4), u[i].x, u[i].y);
                    if (sc) rmw_add2(sa1 + t[i] * (NSC * 4), u[i].x, u[i].y);
                    if (cn) scnt[rs * NT + t[i]] += 1.0f;
                }
            }
        }
    }
    __syncthreads();

    // reduce RS copies, push to global with atomics
    for (int i = tid; i < NT * DIMX; i += 256) {
        float s = s2[i] + s2[NT*DIMX + i] + s2[2*NT*DIMX + i] + s2[3*NT*DIMX + i];
        atomicAdd(&g_scr[i], s);
    }
    for (int i = tid; i < NT * NSC; i += 256) {
        float s = s1[i] + s1[NT*NSC + i] + s1[2*NT*NSC + i] + s1[3*NT*NSC + i];
        atomicAdd(&g_scr[SCR_SUM1 + i], s);
    }
    if (tid < NT) {
        float s = scnt[tid] + scnt[NT + tid] + scnt[2*NT + tid] + scnt[3*NT + tid];
        atomicAdd(&g_scr[SCR_CNT + tid], s);
    }
}

// ---------------------------------------------------------------- table build
__global__ __launch_bounds__(DIMX) void k_tables(const float* __restrict__ w,
                                                 const float* __restrict__ b) {
    const int e = threadIdx.x;
    for (int t = 0; t < NT; t++) {
        float cnt = fmaxf(g_scr[SCR_CNT + t], 1.0f);
        float inv = 1.0f / cnt;
        float A, Bv;
        if (e < NSC) {
            float S2   = g_scr[t * DIMX + e];
            float S1   = g_scr[SCR_SUM1 + t * NSC + e];
            float mean = S1 * inv;
            float var  = S2 * inv - mean * mean;
            float s    = rsqrtf(var + EPSV) * w[t * NF + e];
            A  = s;
            Bv = b[t * NSC + e] - mean * s;
        } else if (e < 64 + 32 * 3) {
            int m    = (e - 64) / 3;
            int base = 64 + m * 3;
            float S2 = g_scr[t * DIMX + base] + g_scr[t * DIMX + base + 1] +
                       g_scr[t * DIMX + base + 2];
            float fn = S2 * inv * (1.0f / 3.0f);
            A  = rsqrtf(fn + EPSV) * w[t * NF + 64 + m];
            Bv = 0.0f;
        } else {
            int m    = (e - 160) / 5;
            int base = 160 + m * 5;
            float S2 = 0.0f;
#pragma unroll
            for (int j = 0; j < 5; j++) S2 += g_scr[t * DIMX + base + j];
            float fn = S2 * inv * 0.2f;
            A  = rsqrtf(fn + EPSV) * w[t * NF + 96 + m];
            Bv = 0.0f;
        }
        g_A[t * DIMX + e] = A;
        g_B[t * DIMX + e] = Bv;
    }
}

// ---------------------------------------------------------------- apply pass
// Reversed block order (round-5 proven shape), one contiguous 1024-float4
// (16 KB) tile per block, 4 float4 per thread, loads front-batched.
// Streaming stores for the output.
__global__ __launch_bounds__(256) void k_apply(const float4* __restrict__ x4,
                                               const int* __restrict__ ty,
                                               float4* __restrict__ o4,
                                               int n4) {
    const unsigned chunk = gridDim.x - 1u - blockIdx.x;
    const unsigned ibase = chunk * 1024u + threadIdx.x;

    const float4* A4 = reinterpret_cast<const float4*>(g_A);
    const float4* B4 = reinterpret_cast<const float4*>(g_B);

    unsigned idx[4];
    bool     g[4];
    float4   xv[4], a[4], bb[4];
    unsigned k[4];

#pragma unroll
    for (int j = 0; j < 4; j++) {
        idx[j] = ibase + j * 256u;
        g[j]   = idx[j] < (unsigned)n4;
    }
#pragma unroll
    for (int j = 0; j < 4; j++) {
        if (g[j]) {
            unsigned row = idx[j] / 60u;
            unsigned q   = idx[j] - row * 60u;
            int t = __ldg(ty + row);
            k[j]  = t * 60u + q;
            xv[j] = x4[idx[j]];
        }
    }
#pragma unroll
    for (int j = 0; j < 4; j++) {
        if (g[j]) { a[j] = A4[k[j]]; bb[j] = B4[k[j]]; }
    }
#pragma unroll
    for (int j = 0; j < 4; j++) {
        if (g[j]) {
            float4 o;
            o.x = fmaf(xv[j].x, a[j].x, bb[j].x);
            o.y = fmaf(xv[j].y, a[j].y, bb[j].y);
            o.z = fmaf(xv[j].z, a[j].z, bb[j].z);
            o.w = fmaf(xv[j].w, a[j].w, bb[j].w);
            __stcs(&o4[idx[j]], o);
        }
    }
}

// ---------------------------------------------------------------- launch
extern "C" void kernel_launch(void* const* d_in, const int* in_sizes, int n_in,
                              void* d_out, int out_size) {
    const float* x  = (const float*)d_in[0];
    const int*   ty = (const int*)d_in[1];
    const float* w  = (const float*)d_in[2];
    const float* b  = (const float*)d_in[3];

    int batch = in_sizes[0] / DIMX;

    k_zero<<<(SCR_SIZE + 255) / 256, 256>>>();
    k_stats<<<592, 256>>>(x, ty, batch);
    k_tables<<<1, DIMX>>>(w, b);

    int n4 = batch * (DIMX / 4);
    k_apply<<<(n4 + 1023) / 1024, 256>>>((const float4*)x, ty, (float4*)d_out, n4);
}

// round 12
// speedup vs baseline: 1.1570x; 1.0168x over previous
#include <cuda_runtime.h>

#define NT   10
#define DIMX 240
#define NSC  64
#define NF   112
#define EPSV 1e-5f
#define RS   4           // replicated accumulator copies (row-subgroups)
#define NBLK 592

// scratch layout: [sum2: NT*DIMX][sum1: NT*NSC][cnt: NT]
#define SCR_SUM1 (NT*DIMX)
#define SCR_CNT  (NT*DIMX + NT*NSC)
#define SCR_SIZE (NT*DIMX + NT*NSC + NT)

__device__ float    g_scr[SCR_SIZE];      // static zero-init; re-zeroed by k_apply
__device__ unsigned g_done;               // stats arrival counter (reset by last block)
__device__ __align__(16) float g_A[NT*DIMX];
__device__ __align__(16) float g_B[NT*DIMX];

// packed-f32x2 shared-memory RMW: s[0..3] += v*v
__device__ __forceinline__ void rmw_fma2(unsigned sa, unsigned long long v01,
                                         unsigned long long v23) {
    asm volatile(
        "{\n\t"
        ".reg .b64 a0, a1;\n\t"
        "ld.shared.v2.b64 {a0, a1}, [%0];\n\t"
        "fma.rn.f32x2 a0, %1, %1, a0;\n\t"
        "fma.rn.f32x2 a1, %2, %2, a1;\n\t"
        "st.shared.v2.b64 [%0], {a0, a1};\n\t"
        "}"
        :: "r"(sa), "l"(v01), "l"(v23));
}

// packed-f32x2 shared-memory RMW: s[0..3] += v
__device__ __forceinline__ void rmw_add2(unsigned sa, unsigned long long v01,
                                         unsigned long long v23) {
    asm volatile(
        "{\n\t"
        ".reg .b64 a0, a1;\n\t"
        "ld.shared.v2.b64 {a0, a1}, [%0];\n\t"
        "add.rn.f32x2 a0, a0, %1;\n\t"
        "add.rn.f32x2 a1, a1, %2;\n\t"
        "st.shared.v2.b64 [%0], {a0, a1};\n\t"
        "}"
        :: "r"(sa), "l"(v01), "l"(v23));
}

// load one thread-pack: 4 contiguous rows (values + types)
__device__ __forceinline__ void load_pack(const float* __restrict__ x,
                                          const int* __restrict__ ty,
                                          int batch, int r0, int c,
                                          ulonglong2* u, int* t, bool* g) {
#pragma unroll
    for (int i = 0; i < 4; i++) {
        int r = r0 + i;
        g[i] = (r < batch);
        if (g[i]) u[i] = __ldg((const ulonglong2*)(x + (size_t)r * DIMX + c));
    }
    if (r0 + 3 < batch) {
        int4 ta = __ldg((const int4*)(ty + r0));
        t[0] = ta.x; t[1] = ta.y; t[2] = ta.z; t[3] = ta.w;
    } else {
#pragma unroll
        for (int i = 0; i < 4; i++) t[i] = g[i] ? __ldg(ty + r0 + i) : 0;
    }
}

// ---------------------------------------------------------------- stats pass
// Grid-strided, blockDim = 256 (threads 0..239 active in main loop).
//   rs = tid/60 : accumulator copy; owns rows base+4*rs .. base+4*rs+3
//   c4 = tid%60 : float4 column group
// Software-pipelined: next iteration's 5 LDGs issue before this iteration's
// smem RMWs. Last block to finish also builds the A/B tables (fused k_tables).
__global__ __launch_bounds__(256) void k_stats(const float* __restrict__ x,
                                               const int* __restrict__ ty,
                                               const float* __restrict__ w,
                                               const float* __restrict__ b,
                                               int batch) {
    __shared__ __align__(16) float s2[RS * NT * DIMX];
    __shared__ __align__(16) float s1[RS * NT * NSC];
    __shared__ float scnt[RS * NT];
    __shared__ unsigned sIsLast;

    const int tid = threadIdx.x;
    for (int i = tid; i < RS * NT * DIMX; i += 256) s2[i] = 0.0f;
    for (int i = tid; i < RS * NT * NSC;  i += 256) s1[i] = 0.0f;
    if (tid < RS * NT) scnt[tid] = 0.0f;
    __syncthreads();

    const int  rs  = tid / 60;
    const int  c4  = tid - rs * 60;
    const int  c   = c4 * 4;
    const bool act = (tid < 240);
    const bool sc  = act && (c4 < 16);   // scalar columns
    const bool cn  = act && (c4 == 0);   // count owner

    const unsigned sa2 = (unsigned)__cvta_generic_to_shared(s2)
                       + (rs * NT * DIMX + c) * 4u;
    const unsigned sa1 = (unsigned)__cvta_generic_to_shared(s1)
                       + (rs * NT * NSC + c) * 4u;

    const int step = gridDim.x * 16;
    int base = blockIdx.x * 16;

    ulonglong2 u[4];  int t[4];  bool g[4];
    if (act && base < batch)
        load_pack(x, ty, batch, base + rs * 4, c, u, t, g);

    for (; base < batch; ) {
        const int nbase = base + step;
        ulonglong2 un[4];  int tn[4];  bool gn[4];
        if (act && nbase < batch)                     // prefetch next pack
            load_pack(x, ty, batch, nbase + rs * 4, c, un, tn, gn);

        if (act) {
#pragma unroll
            for (int i = 0; i < 4; i++) {
                if (g[i]) {
                    rmw_fma2(sa2 + t[i] * (DIMX * 4), u[i].x, u[i].y);
                    if (sc) rmw_add2(sa1 + t[i] * (NSC * 4), u[i].x, u[i].y);
                    if (cn) scnt[rs * NT + t[i]] += 1.0f;
                }
            }
        }
        base = nbase;
#pragma unroll
        for (int i = 0; i < 4; i++) { u[i] = un[i]; t[i] = tn[i]; g[i] = gn[i]; }
    }
    __syncthreads();

    // reduce RS copies, push to global with atomics
    for (int i = tid; i < NT * DIMX; i += 256) {
        float s = s2[i] + s2[NT*DIMX + i] + s2[2*NT*DIMX + i] + s2[3*NT*DIMX + i];
        atomicAdd(&g_scr[i], s);
    }
    for (int i = tid; i < NT * NSC; i += 256) {
        float s = s1[i] + s1[NT*NSC + i] + s1[2*NT*NSC + i] + s1[3*NT*NSC + i];
        atomicAdd(&g_scr[SCR_SUM1 + i], s);
    }
    if (tid < NT) {
        float s = scnt[tid] + scnt[NT + tid] + scnt[2*NT + tid] + scnt[3*NT + tid];
        atomicAdd(&g_scr[SCR_CNT + tid], s);
    }

    // ---- fused table build: last block to arrive does it ----
    __threadfence();
    __syncthreads();
    if (tid == 0)
        sIsLast = (atomicAdd(&g_done, 1u) == gridDim.x - 1u);
    __syncthreads();
    if (!sIsLast) return;
    __threadfence();                      // acquire all blocks' atomics

    const int e = tid;
    if (e < DIMX) {
        for (int tt = 0; tt < NT; tt++) {
            float cnt = fmaxf(g_scr[SCR_CNT + tt], 1.0f);
            float inv = 1.0f / cnt;
            float A, Bv;
            if (e < NSC) {
                float S2   = g_scr[tt * DIMX + e];
                float S1   = g_scr[SCR_SUM1 + tt * NSC + e];
                float mean = S1 * inv;
                float var  = S2 * inv - mean * mean;
                float s    = rsqrtf(var + EPSV) * w[tt * NF + e];
                A  = s;
                Bv = b[tt * NSC + e] - mean * s;
            } else if (e < 64 + 32 * 3) {
                int m    = (e - 64) / 3;
                int bs   = 64 + m * 3;
                float S2 = g_scr[tt * DIMX + bs] + g_scr[tt * DIMX + bs + 1] +
                           g_scr[tt * DIMX + bs + 2];
                float fn = S2 * inv * (1.0f / 3.0f);
                A  = rsqrtf(fn + EPSV) * w[tt * NF + 64 + m];
                Bv = 0.0f;
            } else {
                int m    = (e - 160) / 5;
                int bs   = 160 + m * 5;
                float S2 = 0.0f;
#pragma unroll
                for (int j = 0; j < 5; j++) S2 += g_scr[tt * DIMX + bs + j];
                float fn = S2 * inv * 0.2f;
                A  = rsqrtf(fn + EPSV) * w[tt * NF + 96 + m];
                Bv = 0.0f;
            }
            g_A[tt * DIMX + e] = A;
            g_B[tt * DIMX + e] = Bv;
        }
    }
    if (tid == 0) g_done = 0;             // reset for next graph replay
}

// ---------------------------------------------------------------- apply pass
// Reversed block order, one contiguous 1024-float4 (16 KB) tile per block,
// 4 float4 per thread, loads front-batched, streaming stores.
// Block 0 also re-zeros the stats scratch for the next replay (fused k_zero).
__global__ __launch_bounds__(256) void k_apply(const float4* __restrict__ x4,
                                               const int* __restrict__ ty,
                                               float4* __restrict__ o4,
                                               int n4) {
    if (blockIdx.x == 0) {                 // g_scr is dead now (tables built)
        for (int i = threadIdx.x; i < SCR_SIZE; i += 256) g_scr[i] = 0.0f;
    }

    const unsigned chunk = gridDim.x - 1u - blockIdx.x;
    const unsigned ibase = chunk * 1024u + threadIdx.x;

    const float4* A4 = reinterpret_cast<const float4*>(g_A);
    const float4* B4 = reinterpret_cast<const float4*>(g_B);

    unsigned idx[4];
    bool     g[4];
    float4   xv[4], a[4], bb[4];
    unsigned k[4];

#pragma unroll
    for (int j = 0; j < 4; j++) {
        idx[j] = ibase + j * 256u;
        g[j]   = idx[j] < (unsigned)n4;
    }
#pragma unroll
    for (int j = 0; j < 4; j++) {
        if (g[j]) {
            unsigned row = idx[j] / 60u;
            unsigned q   = idx[j] - row * 60u;
            int t = __ldg(ty + row);
            k[j]  = t * 60u + q;
            xv[j] = x4[idx[j]];
        }
    }
#pragma unroll
    for (int j = 0; j < 4; j++) {
        if (g[j]) { a[j] = A4[k[j]]; bb[j] = B4[k[j]]; }
    }
#pragma unroll
    for (int j = 0; j < 4; j++) {
        if (g[j]) {
            float4 o;
            o.x = fmaf(xv[j].x, a[j].x, bb[j].x);
            o.y = fmaf(xv[j].y, a[j].y, bb[j].y);
            o.z = fmaf(xv[j].z, a[j].z, bb[j].z);
            o.w = fmaf(xv[j].w, a[j].w, bb[j].w);
            __stcs(&o4[idx[j]], o);
        }
    }
}

// ---------------------------------------------------------------- launch
extern "C" void kernel_launch(void* const* d_in, const int* in_sizes, int n_in,
                              void* d_out, int out_size) {
    const float* x  = (const float*)d_in[0];
    const int*   ty = (const int*)d_in[1];
    const float* w  = (const float*)d_in[2];
    const float* b  = (const float*)d_in[3];

    int batch = in_sizes[0] / DIMX;

    k_stats<<<NBLK, 256>>>(x, ty, w, b, batch);

    int n4 = batch * (DIMX / 4);
    k_apply<<<(n4 + 1023) / 1024, 256>>>((const float4*)x, ty, (float4*)d_out, n4);
}